// round 2
// baseline (speedup 1.0000x reference)
#include <cuda_runtime.h>
#include <math.h>

// Problem constants
#define B_SZ   2048
#define N_TOK  64
#define DIMC   512
#define HEADS  16
#define HDIM   32
#define QKVD   1536
#define M_ROWS (B_SZ * N_TOK)   // 131072

// Scratch (device globals — allocation-free per harness rules)
__device__ float g_qkv[(long long)M_ROWS * QKVD]; // 768 MB
__device__ float g_attn[(long long)M_ROWS * DIMC]; // 256 MB
__device__ float g_Ks[N_TOK * N_TOK];

// ---------------------------------------------------------------------------
// Kernel 0: row-normalized Gaussian kernel K_sigma [64 x 64]
// ---------------------------------------------------------------------------
__global__ void ks_kernel() {
    int i = threadIdx.x;  // 0..63
    if (i >= 64) return;
    float yi = (float)(i >> 3), xi = (float)(i & 7);
    const float inv2s2 = 1.0f / (2.0f * 0.39f * 0.39f);
    float s = 0.0f;
    for (int j = 0; j < 64; j++) {
        float dy = yi - (float)(j >> 3);
        float dx = xi - (float)(j & 7);
        s += expf(-(dy * dy + dx * dx) * inv2s2);
    }
    float invs = 1.0f / s;
    for (int j = 0; j < 64; j++) {
        float dy = yi - (float)(j >> 3);
        float dx = xi - (float)(j & 7);
        g_Ks[i * 64 + j] = expf(-(dy * dy + dx * dx) * inv2s2) * invs;
    }
}

// ---------------------------------------------------------------------------
// Tiled fp32 SGEMM + bias: C[M,N] = A[M,K] @ B[K,N] + bias[N]
// BM=BN=128, BK=16, 256 threads, 8x8 per-thread microtile.
// Requires M%128==0, N%128==0, K%16==0 (true for all our shapes).
// ---------------------------------------------------------------------------
__global__ __launch_bounds__(256) void sgemm_bias_kernel(
    const float* __restrict__ A, const float* __restrict__ B,
    const float* __restrict__ bias, float* __restrict__ C,
    int M, int N, int K)
{
    __shared__ float As[16][128];  // transposed: As[k][m]
    __shared__ float Bs[16][128];  // Bs[k][n]

    const int tid = threadIdx.x;
    const int tx = tid & 15;       // n-dir thread
    const int ty = tid >> 4;       // m-dir thread
    const int bx = blockIdx.x;     // n tile
    const int by = blockIdx.y;     // m tile

    const float* Ab = A + (size_t)by * 128 * K;
    const float* Bb = B + (size_t)bx * 128;

    float acc[8][8];
#pragma unroll
    for (int i = 0; i < 8; i++)
#pragma unroll
        for (int j = 0; j < 8; j++) acc[i][j] = 0.0f;

    // A-tile loader mapping: 128 rows x 16 cols; two float4 per thread
    const int arow  = tid >> 2;       // 0..63
    const int acol  = (tid & 3) * 4;  // 0,4,8,12
    // B-tile loader mapping: 16 rows x 128 cols; two float4 per thread
    const int brow  = tid >> 5;       // 0..7
    const int bcol  = (tid & 31) * 4; // 0..124

    for (int kt = 0; kt < K; kt += 16) {
        float4 a0 = *(const float4*)(Ab + (size_t)arow * K + kt + acol);
        float4 a1 = *(const float4*)(Ab + (size_t)(arow + 64) * K + kt + acol);
        float4 b0 = *(const float4*)(Bb + (size_t)(kt + brow) * N + bcol);
        float4 b1 = *(const float4*)(Bb + (size_t)(kt + brow + 8) * N + bcol);

        __syncthreads();   // previous iteration's compute done

        As[acol + 0][arow] = a0.x;  As[acol + 1][arow] = a0.y;
        As[acol + 2][arow] = a0.z;  As[acol + 3][arow] = a0.w;
        As[acol + 0][arow + 64] = a1.x;  As[acol + 1][arow + 64] = a1.y;
        As[acol + 2][arow + 64] = a1.z;  As[acol + 3][arow + 64] = a1.w;
        *(float4*)&Bs[brow][bcol]     = b0;
        *(float4*)&Bs[brow + 8][bcol] = b1;

        __syncthreads();

#pragma unroll
        for (int kk = 0; kk < 16; kk++) {
            float4 av0 = *(const float4*)&As[kk][ty * 8];
            float4 av1 = *(const float4*)&As[kk][ty * 8 + 4];
            float4 bv0 = *(const float4*)&Bs[kk][tx * 8];
            float4 bv1 = *(const float4*)&Bs[kk][tx * 8 + 4];
            float a[8] = {av0.x, av0.y, av0.z, av0.w, av1.x, av1.y, av1.z, av1.w};
            float b[8] = {bv0.x, bv0.y, bv0.z, bv0.w, bv1.x, bv1.y, bv1.z, bv1.w};
#pragma unroll
            for (int i = 0; i < 8; i++)
#pragma unroll
                for (int j = 0; j < 8; j++) acc[i][j] += a[i] * b[j];
        }
    }

    const int row0 = by * 128 + ty * 8;
    const int col0 = bx * 128 + tx * 8;
    float4 bs0 = *(const float4*)(bias + col0);
    float4 bs1 = *(const float4*)(bias + col0 + 4);
#pragma unroll
    for (int i = 0; i < 8; i++) {
        float4 o0 = make_float4(acc[i][0] + bs0.x, acc[i][1] + bs0.y,
                                acc[i][2] + bs0.z, acc[i][3] + bs0.w);
        float4 o1 = make_float4(acc[i][4] + bs1.x, acc[i][5] + bs1.y,
                                acc[i][6] + bs1.z, acc[i][7] + bs1.w);
        float* crow = C + (size_t)(row0 + i) * N + col0;
        *(float4*)(crow)     = o0;
        *(float4*)(crow + 4) = o1;
    }
}

// ---------------------------------------------------------------------------
// Kernel 2: fused per-(batch, head) attention.
// One CTA of 128 threads per (b,h). q,k,v are [64,32] slices of g_qkv.
// logits = (q @ k^T * scale) * Ks, softmax over last dim, O = P @ v.
// Output layout: g_attn[b, n, h*32 + d]  (== transpose(0,2,1,3).reshape)
// ---------------------------------------------------------------------------
__global__ __launch_bounds__(128) void attn_kernel(
    const float* __restrict__ qkv, const float* __restrict__ Ks,
    float* __restrict__ outp)
{
    __shared__ float shQ[64][33];
    __shared__ float shK[64][33];
    __shared__ float shV[64][33];
    __shared__ float shS[64][65];

    const int bh = blockIdx.x;
    const int b = bh >> 4;
    const int h = bh & 15;
    const int tid = threadIdx.x;

    const float* base = qkv + (size_t)b * 64 * QKVD + h * HDIM;

    // Load q (col offset 0), k (+512), v (+1024): 512 float4 per matrix
    for (int idx = tid; idx < 512; idx += 128) {
        int n = idx >> 3;
        int c = (idx & 7) * 4;
        const float* rp = base + (size_t)n * QKVD + c;
        float4 qv = *(const float4*)(rp);
        float4 kv = *(const float4*)(rp + 512);
        float4 vv = *(const float4*)(rp + 1024);
        shQ[n][c] = qv.x; shQ[n][c + 1] = qv.y; shQ[n][c + 2] = qv.z; shQ[n][c + 3] = qv.w;
        shK[n][c] = kv.x; shK[n][c + 1] = kv.y; shK[n][c + 2] = kv.z; shK[n][c + 3] = kv.w;
        shV[n][c] = vv.x; shV[n][c + 1] = vv.y; shV[n][c + 2] = vv.z; shV[n][c + 3] = vv.w;
    }
    __syncthreads();

    const int row  = tid >> 1;   // 0..63
    const int half = tid & 1;    // lane pair shares a row

    float qr[32];
#pragma unroll
    for (int d = 0; d < 32; d++) qr[d] = shQ[row][d];

    const float scale = 0.17677669529663687f;  // 32^-0.5
    float lv[32];
    float m = -1e30f;
#pragma unroll
    for (int jj = 0; jj < 32; jj++) {
        int j = half * 32 + jj;
        float s = 0.0f;
#pragma unroll
        for (int d = 0; d < 32; d++) s += qr[d] * shK[j][d];
        s = s * scale * Ks[row * 64 + j];
        lv[jj] = s;
        m = fmaxf(m, s);
    }
    m = fmaxf(m, __shfl_xor_sync(0xffffffffu, m, 1));
    float sum = 0.0f;
#pragma unroll
    for (int jj = 0; jj < 32; jj++) {
        float e = expf(lv[jj] - m);
        lv[jj] = e;
        sum += e;
    }
    sum += __shfl_xor_sync(0xffffffffu, sum, 1);
    float inv = 1.0f / sum;
#pragma unroll
    for (int jj = 0; jj < 32; jj++) shS[row][half * 32 + jj] = lv[jj] * inv;
    __syncthreads();

    // O[row, half*16 .. +15] = P[row,:] @ V
    float acc[16];
#pragma unroll
    for (int dd = 0; dd < 16; dd++) acc[dd] = 0.0f;
    for (int j = 0; j < 64; j++) {
        float p = shS[row][j];
        const float* vrow = &shV[j][half * 16];
#pragma unroll
        for (int dd = 0; dd < 16; dd++) acc[dd] += p * vrow[dd];
    }

    float* orow = outp + (size_t)(b * 64 + row) * DIMC + h * HDIM + half * 16;
#pragma unroll
    for (int dd = 0; dd < 16; dd += 4) {
        float4 o = make_float4(acc[dd], acc[dd + 1], acc[dd + 2], acc[dd + 3]);
        *(float4*)(orow + dd) = o;
    }
}

// ---------------------------------------------------------------------------
// Launcher (graph-capturable: kernel launches only)
// ---------------------------------------------------------------------------
extern "C" void kernel_launch(void* const* d_in, const int* in_sizes, int n_in,
                              void* d_out, int out_size)
{
    const float* x      = (const float*)d_in[0];
    const float* w_qkv  = (const float*)d_in[1];
    const float* b_qkv  = (const float*)d_in[2];
    const float* w_proj = (const float*)d_in[3];
    const float* b_proj = (const float*)d_in[4];
    float* out = (float*)d_out;

    float *qkv_ptr, *attn_ptr, *ks_ptr;
    cudaGetSymbolAddress((void**)&qkv_ptr, g_qkv);
    cudaGetSymbolAddress((void**)&attn_ptr, g_attn);
    cudaGetSymbolAddress((void**)&ks_ptr, g_Ks);

    // 0) Gaussian kernel table
    ks_kernel<<<1, 64>>>();

    // 1) qkv = x @ w_qkv + b_qkv   [131072 x 1536]
    dim3 g1(QKVD / 128, M_ROWS / 128);
    sgemm_bias_kernel<<<g1, 256>>>(x, w_qkv, b_qkv, qkv_ptr, M_ROWS, QKVD, DIMC);

    // 2) windowed Gaussian attention per (b, h)
    attn_kernel<<<B_SZ * HEADS, 128>>>(qkv_ptr, ks_ptr, attn_ptr);

    // 3) out = attn @ w_proj + b_proj   [131072 x 512]
    dim3 g2(DIMC / 128, M_ROWS / 128);
    sgemm_bias_kernel<<<g2, 256>>>(attn_ptr, w_proj, b_proj, out, M_ROWS, DIMC, DIMC);
}

// round 8
// speedup vs baseline: 1.7535x; 1.7535x over previous
#include <cuda_runtime.h>
#include <cuda_bf16.h>
#include <cstdint>
#include <math.h>

// Problem constants
#define B_SZ   2048
#define N_TOK  64
#define DIMC   512
#define HEADS  16
#define HDIM   32
#define QKVD   1536
#define M_ROWS (B_SZ * N_TOK)   // 131072
#define KDIM   512               // inner dim of both GEMMs

// ---------------------------------------------------------------------------
// Device scratch (allocation-free per harness rules)
// ---------------------------------------------------------------------------
__device__ float g_qkv[(long long)M_ROWS * QKVD];            // 768 MB fp32
__device__ float g_Ks[N_TOK * N_TOK];
__device__ __nv_bfloat16 g_x_hi[(long long)M_ROWS * KDIM];   // 134 MB
__device__ __nv_bfloat16 g_x_lo[(long long)M_ROWS * KDIM];
__device__ __nv_bfloat16 g_attn_hi[(long long)M_ROWS * DIMC];
__device__ __nv_bfloat16 g_attn_lo[(long long)M_ROWS * DIMC];
__device__ __nv_bfloat16 g_wqkvT_hi[QKVD * KDIM];            // [N][K]
__device__ __nv_bfloat16 g_wqkvT_lo[QKVD * KDIM];
__device__ __nv_bfloat16 g_wprojT_hi[DIMC * KDIM];
__device__ __nv_bfloat16 g_wprojT_lo[DIMC * KDIM];

// ---------------------------------------------------------------------------
// PTX helpers — ONLY plain sm_80+ features (no tcgen05: harness targets sm_103
// without the 'a' feature set, which rejects all tcgen05/TMEM instructions).
// ---------------------------------------------------------------------------
__device__ __forceinline__ uint32_t smem_u32(const void* p) {
    uint32_t a;
    asm("{ .reg .u64 t; cvta.to.shared.u64 t, %1; cvt.u32.u64 %0, t; }" : "=r"(a) : "l"(p));
    return a;
}
__device__ __forceinline__ void cp16(uint32_t saddr, const void* g) {
    asm volatile("cp.async.cg.shared.global [%0], [%1], 16;" :: "r"(saddr), "l"(g));
}
#define CP_COMMIT() asm volatile("cp.async.commit_group;" ::: "memory")
#define CP_WAIT1()  asm volatile("cp.async.wait_group 1;" ::: "memory")
#define CP_WAIT0()  asm volatile("cp.async.wait_group 0;" ::: "memory")

__device__ __forceinline__ void ldsm4(uint32_t* r, uint32_t addr) {
    asm volatile("ldmatrix.sync.aligned.m8n8.x4.shared.b16 {%0,%1,%2,%3}, [%4];"
                 : "=r"(r[0]), "=r"(r[1]), "=r"(r[2]), "=r"(r[3]) : "r"(addr));
}
__device__ __forceinline__ void mma16816(float* d, const uint32_t* a, const uint32_t* b) {
    asm volatile("mma.sync.aligned.m16n8k16.row.col.f32.bf16.bf16.f32 "
                 "{%0,%1,%2,%3}, {%4,%5,%6,%7}, {%8,%9}, {%0,%1,%2,%3};"
                 : "+f"(d[0]), "+f"(d[1]), "+f"(d[2]), "+f"(d[3])
                 : "r"(a[0]), "r"(a[1]), "r"(a[2]), "r"(a[3]), "r"(b[0]), "r"(b[1]));
}

// ---------------------------------------------------------------------------
// Kernel 0: row-normalized Gaussian kernel K_sigma [64 x 64]
// ---------------------------------------------------------------------------
__global__ void ks_kernel() {
    int i = threadIdx.x;
    if (i >= 64) return;
    float yi = (float)(i >> 3), xi = (float)(i & 7);
    const float inv2s2 = 1.0f / (2.0f * 0.39f * 0.39f);
    float s = 0.0f;
    for (int j = 0; j < 64; j++) {
        float dy = yi - (float)(j >> 3), dx = xi - (float)(j & 7);
        s += expf(-(dy * dy + dx * dx) * inv2s2);
    }
    float invs = 1.0f / s;
    for (int j = 0; j < 64; j++) {
        float dy = yi - (float)(j >> 3), dx = xi - (float)(j & 7);
        g_Ks[i * 64 + j] = expf(-(dy * dy + dx * dx) * inv2s2) * invs;
    }
}

// ---------------------------------------------------------------------------
// Weight prep: w [K][N] row-major fp32 -> [N][K] bf16 hi/lo
// ---------------------------------------------------------------------------
__global__ void prep_w_kernel(const float* __restrict__ w,
                              __nv_bfloat16* __restrict__ hi,
                              __nv_bfloat16* __restrict__ lo, int N) {
    long long idx = (long long)blockIdx.x * 256 + threadIdx.x;
    if (idx >= (long long)N * KDIM) return;
    int n = (int)(idx >> 9);
    int k = (int)(idx & 511);
    float v = w[(size_t)k * N + n];
    __nv_bfloat16 h = __float2bfloat16(v);
    hi[idx] = h;
    lo[idx] = __float2bfloat16(v - __bfloat162float(h));
}

// ---------------------------------------------------------------------------
// Activation split: fp32 [M*512] -> bf16 hi/lo (vectorized by 4)
// ---------------------------------------------------------------------------
__global__ void split_x_kernel(const float* __restrict__ src,
                               __nv_bfloat16* __restrict__ hi,
                               __nv_bfloat16* __restrict__ lo, long long n4) {
    long long i = (long long)blockIdx.x * 256 + threadIdx.x;
    if (i >= n4) return;
    long long idx = i * 4;
    float4 v = *(const float4*)(src + idx);
    __nv_bfloat16 hx = __float2bfloat16(v.x), hy = __float2bfloat16(v.y);
    __nv_bfloat16 hz = __float2bfloat16(v.z), hw = __float2bfloat16(v.w);
    __nv_bfloat162 h01, h23, l01, l23;
    h01.x = hx; h01.y = hy; h23.x = hz; h23.y = hw;
    l01.x = __float2bfloat16(v.x - __bfloat162float(hx));
    l01.y = __float2bfloat16(v.y - __bfloat162float(hy));
    l23.x = __float2bfloat16(v.z - __bfloat162float(hz));
    l23.y = __float2bfloat16(v.w - __bfloat162float(hw));
    *(__nv_bfloat162*)(hi + idx)     = h01;
    *(__nv_bfloat162*)(hi + idx + 2) = h23;
    *(__nv_bfloat162*)(lo + idx)     = l01;
    *(__nv_bfloat162*)(lo + idx + 2) = l23;
}

// ---------------------------------------------------------------------------
// Warp-MMA bf16-split GEMM: C[M,Ntot] = A[M,512] @ B[512,Ntot] + bias
// A,B pre-split bf16 (A [M][K] row-major, B [N][K] = B^T row-major).
// CTA tile 128x128, BK=64, 2-stage cp.async pipeline, 8 warps (64x32 each).
// acc += Ah*Bh + Ah*Bl + Al*Bh   (3-term split, ~1e-5 rel err)
// ---------------------------------------------------------------------------
#define STG 65536           // stage stride: 4 buffers x (128 x 64 x 2B)
#define OFF_AH 0
#define OFF_AL 16384
#define OFF_BH 32768
#define OFF_BL 49152
#define GEMM_SMEM (2 * STG) // 128 KB

__global__ __launch_bounds__(256, 1) void gemm_mma_kernel(
    const __nv_bfloat16* __restrict__ Ah, const __nv_bfloat16* __restrict__ Al,
    const __nv_bfloat16* __restrict__ Bh, const __nv_bfloat16* __restrict__ Bl,
    const float* __restrict__ bias, float* __restrict__ C, int Ntot)
{
    extern __shared__ char smem[];
    const uint32_t sb = smem_u32(smem);
    const int tid = threadIdx.x;
    const int w = tid >> 5, lane = tid & 31;
    const int m0 = blockIdx.y * 128, n0 = blockIdx.x * 128;
    const int wm = (w >> 2) * 64, wn = (w & 3) * 32;

    auto load_stage = [&](int s, int kt) {
        const uint32_t stb = sb + s * STG;
#pragma unroll
        for (int i = 0; i < 4; i++) {
            int id = i * 256 + tid;          // 0..1023
            int r = id >> 3, c = id & 7;     // row, 16B-chunk
            uint32_t sw = (uint32_t)(r * 128 + ((c ^ (r & 7)) << 4));
            size_t ga = (size_t)(m0 + r) * KDIM + kt + c * 8;
            size_t gb = (size_t)(n0 + r) * KDIM + kt + c * 8;
            cp16(stb + OFF_AH + sw, Ah + ga);
            cp16(stb + OFF_AL + sw, Al + ga);
            cp16(stb + OFF_BH + sw, Bh + gb);
            cp16(stb + OFF_BL + sw, Bl + gb);
        }
        CP_COMMIT();
    };

    float acc[4][4][4];
#pragma unroll
    for (int i = 0; i < 4; i++)
#pragma unroll
        for (int j = 0; j < 4; j++)
#pragma unroll
            for (int q = 0; q < 4; q++) acc[i][j][q] = 0.0f;

    load_stage(0, 0);
    load_stage(1, 64);

    for (int ch = 0; ch < 8; ch++) {
        if (ch == 7) CP_WAIT0(); else CP_WAIT1();
        __syncthreads();
        const uint32_t stb = sb + (ch & 1) * STG;

#pragma unroll
        for (int kt = 0; kt < 4; kt++) {
            uint32_t ah[4][4], al[4][4];
#pragma unroll
            for (int mt = 0; mt < 4; mt++) {
                int r = wm + mt * 16 + (lane & 15);
                int cid = kt * 2 + (lane >> 4);
                uint32_t off = (uint32_t)(r * 128 + ((cid ^ (r & 7)) << 4));
                ldsm4(ah[mt], stb + OFF_AH + off);
                ldsm4(al[mt], stb + OFF_AL + off);
            }
            uint32_t bh0[4], bh1[4], bl0[4], bl1[4];
            {
                int n = wn + lane;           // 4 n-tiles of 8 rows each
                int c0 = kt * 2;
                uint32_t o0 = (uint32_t)(n * 128 + ((c0 ^ (n & 7)) << 4));
                uint32_t o1 = (uint32_t)(n * 128 + (((c0 + 1) ^ (n & 7)) << 4));
                ldsm4(bh0, stb + OFF_BH + o0);
                ldsm4(bh1, stb + OFF_BH + o1);
                ldsm4(bl0, stb + OFF_BL + o0);
                ldsm4(bl1, stb + OFF_BL + o1);
            }
#pragma unroll
            for (int mt = 0; mt < 4; mt++)
#pragma unroll
                for (int nt = 0; nt < 4; nt++) {
                    uint32_t bh[2] = {bh0[nt], bh1[nt]};
                    uint32_t bl[2] = {bl0[nt], bl1[nt]};
                    mma16816(acc[mt][nt], ah[mt], bh);
                    mma16816(acc[mt][nt], ah[mt], bl);
                    mma16816(acc[mt][nt], al[mt], bh);
                }
        }
        __syncthreads();
        if (ch < 6) load_stage(ch & 1, (ch + 2) * 64);
    }

    // Epilogue: d0,d1 -> (row, col..col+1); d2,d3 -> (row+8, ...)
#pragma unroll
    for (int mt = 0; mt < 4; mt++) {
        int row = m0 + wm + mt * 16 + (lane >> 2);
#pragma unroll
        for (int nt = 0; nt < 4; nt++) {
            int col = n0 + wn + nt * 8 + ((lane & 3) << 1);
            float b0 = bias[col], b1 = bias[col + 1];
            float2 v0 = make_float2(acc[mt][nt][0] + b0, acc[mt][nt][1] + b1);
            float2 v1 = make_float2(acc[mt][nt][2] + b0, acc[mt][nt][3] + b1);
            *(float2*)(C + (size_t)row * Ntot + col)       = v0;
            *(float2*)(C + (size_t)(row + 8) * Ntot + col) = v1;
        }
    }
}

// ---------------------------------------------------------------------------
// Fused per-(batch, head) attention; outputs hi/lo bf16 split for GEMM2.
// ---------------------------------------------------------------------------
__global__ __launch_bounds__(128) void attn_kernel(
    const float* __restrict__ qkv, const float* __restrict__ Ks,
    __nv_bfloat16* __restrict__ out_hi, __nv_bfloat16* __restrict__ out_lo)
{
    __shared__ float shQ[64][33];
    __shared__ float shK[64][33];
    __shared__ float shV[64][33];
    __shared__ float shS[64][65];

    const int bh = blockIdx.x;
    const int b = bh >> 4;
    const int h = bh & 15;
    const int tid = threadIdx.x;

    const float* base = qkv + (size_t)b * 64 * QKVD + h * HDIM;

    for (int idx = tid; idx < 512; idx += 128) {
        int n = idx >> 3;
        int c = (idx & 7) * 4;
        const float* rp = base + (size_t)n * QKVD + c;
        float4 qv = *(const float4*)(rp);
        float4 kv = *(const float4*)(rp + 512);
        float4 vv = *(const float4*)(rp + 1024);
        shQ[n][c] = qv.x; shQ[n][c + 1] = qv.y; shQ[n][c + 2] = qv.z; shQ[n][c + 3] = qv.w;
        shK[n][c] = kv.x; shK[n][c + 1] = kv.y; shK[n][c + 2] = kv.z; shK[n][c + 3] = kv.w;
        shV[n][c] = vv.x; shV[n][c + 1] = vv.y; shV[n][c + 2] = vv.z; shV[n][c + 3] = vv.w;
    }
    __syncthreads();

    const int row  = tid >> 1;
    const int half = tid & 1;

    float qr[32];
#pragma unroll
    for (int d = 0; d < 32; d++) qr[d] = shQ[row][d];

    const float scale = 0.17677669529663687f;
    float lv[32];
    float m = -1e30f;
#pragma unroll
    for (int jj = 0; jj < 32; jj++) {
        int j = half * 32 + jj;
        float s = 0.0f;
#pragma unroll
        for (int d = 0; d < 32; d++) s += qr[d] * shK[j][d];
        s = s * scale * Ks[row * 64 + j];
        lv[jj] = s;
        m = fmaxf(m, s);
    }
    m = fmaxf(m, __shfl_xor_sync(0xffffffffu, m, 1));
    float sum = 0.0f;
#pragma unroll
    for (int jj = 0; jj < 32; jj++) {
        float e = expf(lv[jj] - m);
        lv[jj] = e;
        sum += e;
    }
    sum += __shfl_xor_sync(0xffffffffu, sum, 1);
    float inv = 1.0f / sum;
#pragma unroll
    for (int jj = 0; jj < 32; jj++) shS[row][half * 32 + jj] = lv[jj] * inv;
    __syncthreads();

    float acc[16];
#pragma unroll
    for (int dd = 0; dd < 16; dd++) acc[dd] = 0.0f;
    for (int j = 0; j < 64; j++) {
        float p = shS[row][j];
        const float* vrow = &shV[j][half * 16];
#pragma unroll
        for (int dd = 0; dd < 16; dd++) acc[dd] += p * vrow[dd];
    }

    size_t obase = (size_t)(b * 64 + row) * DIMC + h * HDIM + half * 16;
#pragma unroll
    for (int dd = 0; dd < 16; dd += 2) {
        __nv_bfloat16 h0 = __float2bfloat16(acc[dd]);
        __nv_bfloat16 h1 = __float2bfloat16(acc[dd + 1]);
        __nv_bfloat162 hp, lp;
        hp.x = h0; hp.y = h1;
        lp.x = __float2bfloat16(acc[dd]     - __bfloat162float(h0));
        lp.y = __float2bfloat16(acc[dd + 1] - __bfloat162float(h1));
        *(__nv_bfloat162*)(out_hi + obase + dd) = hp;
        *(__nv_bfloat162*)(out_lo + obase + dd) = lp;
    }
}

// ---------------------------------------------------------------------------
// Launcher
// ---------------------------------------------------------------------------
extern "C" void kernel_launch(void* const* d_in, const int* in_sizes, int n_in,
                              void* d_out, int out_size)
{
    const float* x      = (const float*)d_in[0];
    const float* w_qkv  = (const float*)d_in[1];
    const float* b_qkv  = (const float*)d_in[2];
    const float* w_proj = (const float*)d_in[3];
    const float* b_proj = (const float*)d_in[4];
    float* out = (float*)d_out;

    float *qkv_ptr, *ks_ptr;
    __nv_bfloat16 *xh, *xl, *ath, *atl, *wqh, *wql, *wph, *wpl;
    cudaGetSymbolAddress((void**)&qkv_ptr, g_qkv);
    cudaGetSymbolAddress((void**)&ks_ptr, g_Ks);
    cudaGetSymbolAddress((void**)&xh, g_x_hi);
    cudaGetSymbolAddress((void**)&xl, g_x_lo);
    cudaGetSymbolAddress((void**)&ath, g_attn_hi);
    cudaGetSymbolAddress((void**)&atl, g_attn_lo);
    cudaGetSymbolAddress((void**)&wqh, g_wqkvT_hi);
    cudaGetSymbolAddress((void**)&wql, g_wqkvT_lo);
    cudaGetSymbolAddress((void**)&wph, g_wprojT_hi);
    cudaGetSymbolAddress((void**)&wpl, g_wprojT_lo);

    cudaFuncSetAttribute(gemm_mma_kernel,
                         cudaFuncAttributeMaxDynamicSharedMemorySize, GEMM_SMEM);

    // 0) prep: Gaussian table, weight transpose+split, activation split
    ks_kernel<<<1, 64>>>();
    prep_w_kernel<<<(QKVD * KDIM + 255) / 256, 256>>>(w_qkv, wqh, wql, QKVD);
    prep_w_kernel<<<(DIMC * KDIM + 255) / 256, 256>>>(w_proj, wph, wpl, DIMC);
    long long n4 = (long long)M_ROWS * KDIM / 4;
    split_x_kernel<<<(int)((n4 + 255) / 256), 256>>>(x, xh, xl, n4);

    // 1) qkv = x @ w_qkv + b_qkv    [131072 x 1536]
    dim3 g1(QKVD / 128, M_ROWS / 128);
    gemm_mma_kernel<<<g1, 256, GEMM_SMEM>>>(xh, xl, wqh, wql, b_qkv, qkv_ptr, QKVD);

    // 2) windowed Gaussian attention per (b, h) -> hi/lo split output
    attn_kernel<<<B_SZ * HEADS, 128>>>(qkv_ptr, ks_ptr, ath, atl);

    // 3) out = attn @ w_proj + b_proj   [131072 x 512]
    dim3 g2(DIMC / 128, M_ROWS / 128);
    gemm_mma_kernel<<<g2, 256, GEMM_SMEM>>>(ath, atl, wph, wpl, b_proj, out, DIMC);
}